// round 14
// baseline (speedup 1.0000x reference)
#include <cuda_runtime.h>

// LightweightConv: depthwise temporal conv with per-head softmax weights.
// B=16, T=4000, C=512, H=8, K=31, PAD=15.
// out[b,t,c] = sum_k softmax(w)[c%8][k] * x[b, t-15+k, c] + bias[c%8]
//
// R14: single-kernel, BARRIER-FREE fusion. Every lane redundantly computes
// the softmax for head (lane&7) in registers, then shfl.idx distributes the
// packed per-pair weights. No SMEM, no __syncthreads -> the main loop keeps
// the exact R6 register-resident structure (best kernel: 48.4us), while the
// second graph node + prep launch (~4-7us of E2E) disappears.

#define B_ 16
#define T_ 4000
#define C_ 512
#define H_ 8
#define K_ 31
#define PAD_ 15
#define TT 24   // t-outputs per thread; ceil(4000/24) = 167 blocks in t

// Packed fp32x2 FMA (sm_100+): d = a*b + c elementwise on two packed floats.
__device__ __forceinline__ unsigned long long ffma2(unsigned long long a,
                                                    unsigned long long b,
                                                    unsigned long long c) {
    unsigned long long d;
    asm("fma.rn.f32x2 %0, %1, %2, %3;" : "=l"(d) : "l"(a), "l"(b), "l"(c));
    return d;
}

// Streaming 8B store (evict-first: output is never re-read; protect L2 halo).
__device__ __forceinline__ void stcs8(float* a, unsigned long long v) {
    asm volatile("st.global.cs.b64 [%0], %1;" :: "l"(a), "l"(v));
}

__device__ __forceinline__ unsigned long long pack2(float lo, float hi) {
    float2 v = make_float2(lo, hi);
    return *reinterpret_cast<unsigned long long*>(&v);
}

__global__ void __launch_bounds__(256, 2)
conv_kernel(const float* __restrict__ x, const float* __restrict__ w,
            const float* __restrict__ bias, float* __restrict__ out) {
    const int tid = threadIdx.x;          // 0..255
    const int lane = tid & 31;
    const int c0 = tid << 1;              // channels c0, c0+1 (contiguous)
    const int p = tid & 3;                // pair type: heads (2p, 2p+1)
    const int b = blockIdx.y;
    const int t0 = blockIdx.x * TT;

    // --- Barrier-free softmax prologue (all in registers). ---
    // Every lane computes softmax of head (lane & 7); lanes 0..7 are the
    // canonical sources for the shfl distribution below.
    unsigned long long wk[K_];
    {
        const int h = lane & 7;
        float v[K_];
        #pragma unroll
        for (int k = 0; k < K_; k++) v[k] = __ldg(w + h * K_ + k);

        float m = v[0];
        #pragma unroll
        for (int k = 1; k < K_; k++) m = fmaxf(m, v[k]);

        float s = 0.0f;
        #pragma unroll
        for (int k = 0; k < K_; k++) { v[k] = __expf(v[k] - m); s += v[k]; }

        const float inv = __frcp_rn(s);
        #pragma unroll
        for (int k = 0; k < K_; k++) v[k] *= inv;

        // Distribute: wk[k] = (softmax[2p][k], softmax[2p+1][k]).
        #pragma unroll
        for (int k = 0; k < K_; k++) {
            const float lo = __shfl_sync(0xffffffffu, v[k], 2 * p);
            const float hi = __shfl_sync(0xffffffffu, v[k], 2 * p + 1);
            wk[k] = pack2(lo, hi);
        }
    }

    const unsigned long long bb =
        pack2(__ldg(bias + 2 * p), __ldg(bias + 2 * p + 1));

    unsigned long long acc[TT];
    #pragma unroll
    for (int j = 0; j < TT; j++) acc[j] = bb;

    const float* xp = x + ((size_t)b * T_) * C_ + c0;

    if (t0 >= PAD_ && t0 + TT + PAD_ <= T_) {
        // Interior fast path: no boundary predicates.
        const float* xq = xp + (size_t)(t0 - PAD_) * C_;
        #pragma unroll
        for (int i = 0; i < TT + 2 * PAD_; i++) {
            const unsigned long long xv =
                *reinterpret_cast<const unsigned long long*>(xq + (size_t)i * C_);
            #pragma unroll
            for (int j = 0; j < TT; j++) {
                if (i - j >= 0 && i - j < K_)   // constant-folds after unroll
                    acc[j] = ffma2(wk[i - j], xv, acc[j]);
            }
        }
        float* op = out + ((size_t)b * T_ + t0) * C_ + c0;
        #pragma unroll
        for (int j = 0; j < TT; j++)
            stcs8(op + (size_t)j * C_, acc[j]);
    } else {
        // Boundary path: zero-padded loads, guarded stores (covers tail block).
        #pragma unroll
        for (int i = 0; i < TT + 2 * PAD_; i++) {
            const int t = t0 - PAD_ + i;
            unsigned long long xv = 0ull;
            if (t >= 0 && t < T_)
                xv = *reinterpret_cast<const unsigned long long*>(xp + (size_t)t * C_);
            #pragma unroll
            for (int j = 0; j < TT; j++) {
                if (i - j >= 0 && i - j < K_)
                    acc[j] = ffma2(wk[i - j], xv, acc[j]);
            }
        }
        float* op = out + ((size_t)b * T_ + t0) * C_ + c0;
        #pragma unroll
        for (int j = 0; j < TT; j++)
            if (t0 + j < T_)
                stcs8(op + (size_t)j * C_, acc[j]);
    }
}

extern "C" void kernel_launch(void* const* d_in, const int* in_sizes, int n_in,
                              void* d_out, int out_size) {
    const float* x    = (const float*)d_in[0];  // (B, T, C)
    const float* w    = (const float*)d_in[1];  // (H, 1, K)
    const float* bias = (const float*)d_in[2];  // (H,)
    float* out = (float*)d_out;                 // (B, T, C)

    dim3 grid((T_ + TT - 1) / TT, B_);
    conv_kernel<<<grid, 256>>>(x, w, bias, out);
}

// round 15
// speedup vs baseline: 1.1027x; 1.1027x over previous
#include <cuda_runtime.h>

// LightweightConv: depthwise temporal conv with per-head softmax weights.
// B=16, T=4000, C=512, H=8, K=31, PAD=15.
// out[b,t,c] = sum_k softmax(w)[c%8][k] * x[b, t-15+k, c] + bias[c%8]
//
// FINAL (best of 14 structural variants; kernel 48.4us at R13):
//  - thread <-> contiguous channel pair, one LDG.64 + FFMA2 (fma.rn.f32x2)
//    per (row, output) covering both channels
//  - softmaxed weights packed per pair-type by a tiny prep kernel, resident
//    in registers for the whole conv kernel
//  - TT=24 outputs/thread (optimum of TT sweep {16,20,24,25,28})
//  - streaming .cs stores (output never re-read; preserves L2 halo)
//  - 2 CTAs/SM. Falsified alternatives: higher occupancy (3x), SMEM/JIT/
//    K-split weights, LDGSTS pipeline, TMA bulk ring, L2 prefetch, and all
//    three softmax-fusion schemes (SMEM+barrier, TMA, register+shfl).

#define B_ 16
#define T_ 4000
#define C_ 512
#define H_ 8
#define K_ 31
#define PAD_ 15
#define TT 24   // t-outputs per thread; ceil(4000/24) = 167 blocks in t

// Packed (per channel-pair) softmaxed weights and bias.
// Pair type p in [0,4): channels (2p, 2p+1) mod 8 -> heads (2p, 2p+1).
__device__ unsigned long long g_wpair[4][K_];
__device__ unsigned long long g_bpair[4];

__global__ void prep_kernel(const float* __restrict__ w,
                            const float* __restrict__ bias) {
    __shared__ float ws[H_][K_];
    int tid = threadIdx.x;
    if (tid < H_) {
        float m = -3.402823466e38f;
        #pragma unroll
        for (int k = 0; k < K_; k++) m = fmaxf(m, w[tid * K_ + k]);
        float e[K_];
        float s = 0.0f;
        #pragma unroll
        for (int k = 0; k < K_; k++) {
            e[k] = expf(w[tid * K_ + k] - m);
            s += e[k];
        }
        float inv = 1.0f / s;
        #pragma unroll
        for (int k = 0; k < K_; k++) ws[tid][k] = e[k] * inv;
    }
    __syncthreads();
    if (tid < 4 * K_) {
        int p = tid / K_;
        int k = tid % K_;
        float2 v = make_float2(ws[2 * p][k], ws[2 * p + 1][k]);
        g_wpair[p][k] = *reinterpret_cast<unsigned long long*>(&v);
    }
    if (tid < 4) {
        float2 v = make_float2(bias[2 * tid], bias[2 * tid + 1]);
        g_bpair[tid] = *reinterpret_cast<unsigned long long*>(&v);
    }
}

// Packed fp32x2 FMA (sm_100+): d = a*b + c elementwise on two packed floats.
__device__ __forceinline__ unsigned long long ffma2(unsigned long long a,
                                                    unsigned long long b,
                                                    unsigned long long c) {
    unsigned long long d;
    asm("fma.rn.f32x2 %0, %1, %2, %3;" : "=l"(d) : "l"(a), "l"(b), "l"(c));
    return d;
}

// Streaming 8B store (evict-first: output is never re-read; protect L2 halo).
__device__ __forceinline__ void stcs8(float* a, unsigned long long v) {
    asm volatile("st.global.cs.b64 [%0], %1;" :: "l"(a), "l"(v));
}

__global__ void __launch_bounds__(256, 2)
conv_kernel(const float* __restrict__ x, float* __restrict__ out) {
    const int tid = threadIdx.x;          // 0..255
    const int c0 = tid << 1;              // channels c0, c0+1 (contiguous)
    const int p = tid & 3;                // pair type: heads (2p, 2p+1)
    const int b = blockIdx.y;
    const int t0 = blockIdx.x * TT;

    // Weights for this channel pair (packed), resident in registers.
    unsigned long long wk[K_];
    #pragma unroll
    for (int k = 0; k < K_; k++) wk[k] = g_wpair[p][k];

    const unsigned long long bb = g_bpair[p];

    unsigned long long acc[TT];
    #pragma unroll
    for (int j = 0; j < TT; j++) acc[j] = bb;

    const float* xp = x + ((size_t)b * T_) * C_ + c0;

    if (t0 >= PAD_ && t0 + TT + PAD_ <= T_) {
        // Interior fast path: no boundary predicates.
        const float* xq = xp + (size_t)(t0 - PAD_) * C_;
        #pragma unroll
        for (int i = 0; i < TT + 2 * PAD_; i++) {
            const unsigned long long xv =
                *reinterpret_cast<const unsigned long long*>(xq + (size_t)i * C_);
            #pragma unroll
            for (int j = 0; j < TT; j++) {
                if (i - j >= 0 && i - j < K_)   // constant-folds after unroll
                    acc[j] = ffma2(wk[i - j], xv, acc[j]);
            }
        }
        float* op = out + ((size_t)b * T_ + t0) * C_ + c0;
        #pragma unroll
        for (int j = 0; j < TT; j++)
            stcs8(op + (size_t)j * C_, acc[j]);
    } else {
        // Boundary path: zero-padded loads, guarded stores (covers tail block).
        #pragma unroll
        for (int i = 0; i < TT + 2 * PAD_; i++) {
            const int t = t0 - PAD_ + i;
            unsigned long long xv = 0ull;
            if (t >= 0 && t < T_)
                xv = *reinterpret_cast<const unsigned long long*>(xp + (size_t)t * C_);
            #pragma unroll
            for (int j = 0; j < TT; j++) {
                if (i - j >= 0 && i - j < K_)
                    acc[j] = ffma2(wk[i - j], xv, acc[j]);
            }
        }
        float* op = out + ((size_t)b * T_ + t0) * C_ + c0;
        #pragma unroll
        for (int j = 0; j < TT; j++)
            if (t0 + j < T_)
                stcs8(op + (size_t)j * C_, acc[j]);
    }
}

extern "C" void kernel_launch(void* const* d_in, const int* in_sizes, int n_in,
                              void* d_out, int out_size) {
    const float* x    = (const float*)d_in[0];  // (B, T, C)
    const float* w    = (const float*)d_in[1];  // (H, 1, K)
    const float* bias = (const float*)d_in[2];  // (H,)
    float* out = (float*)d_out;                 // (B, T, C)

    prep_kernel<<<1, 128>>>(w, bias);

    dim3 grid((T_ + TT - 1) / TT, B_);
    conv_kernel<<<grid, 256>>>(x, out);
}

// round 16
// speedup vs baseline: 1.1103x; 1.0069x over previous
#include <cuda_runtime.h>

// LightweightConv: depthwise temporal conv with per-head softmax weights.
// B=16, T=4000, C=512, H=8, K=31, PAD=15.
// out[b,t,c] = sum_k softmax(w)[c%8][k] * x[b, t-15+k, c] + bias[c%8]
//
// R16: conv kernel identical to the converged best (48.4-48.7us: TT=24,
// weights resident in regs, FFMA2, .cs stores, 2 CTA/SM). New: PDL
// (programmatic dependent launch) overlaps the conv grid's launch latency
// with prep_kernel's execution; conv waits via cudaGridDependencySynchronize
// (one instruction at entry) before reading the packed weights.

#define B_ 16
#define T_ 4000
#define C_ 512
#define H_ 8
#define K_ 31
#define PAD_ 15
#define TT 24   // t-outputs per thread; ceil(4000/24) = 167 blocks in t

// Packed (per channel-pair) softmaxed weights and bias.
// Pair type p in [0,4): channels (2p, 2p+1) mod 8 -> heads (2p, 2p+1).
__device__ unsigned long long g_wpair[4][K_];
__device__ unsigned long long g_bpair[4];

__global__ void prep_kernel(const float* __restrict__ w,
                            const float* __restrict__ bias) {
    __shared__ float ws[H_][K_];
    int tid = threadIdx.x;
    if (tid < H_) {
        float m = -3.402823466e38f;
        #pragma unroll
        for (int k = 0; k < K_; k++) m = fmaxf(m, w[tid * K_ + k]);
        float e[K_];
        float s = 0.0f;
        #pragma unroll
        for (int k = 0; k < K_; k++) {
            e[k] = expf(w[tid * K_ + k] - m);
            s += e[k];
        }
        float inv = 1.0f / s;
        #pragma unroll
        for (int k = 0; k < K_; k++) ws[tid][k] = e[k] * inv;
    }
    __syncthreads();
    if (tid < 4 * K_) {
        int p = tid / K_;
        int k = tid % K_;
        float2 v = make_float2(ws[2 * p][k], ws[2 * p + 1][k]);
        g_wpair[p][k] = *reinterpret_cast<unsigned long long*>(&v);
    }
    if (tid < 4) {
        float2 v = make_float2(bias[2 * tid], bias[2 * tid + 1]);
        g_bpair[tid] = *reinterpret_cast<unsigned long long*>(&v);
    }
    // PDL: make weight tables visible, then allow the dependent conv grid
    // to start (its cudaGridDependencySynchronize sees these writes).
    __syncthreads();
    if (tid == 0) {
        __threadfence();
        cudaTriggerProgrammaticLaunchCompletion();
    }
}

// Packed fp32x2 FMA (sm_100+): d = a*b + c elementwise on two packed floats.
__device__ __forceinline__ unsigned long long ffma2(unsigned long long a,
                                                    unsigned long long b,
                                                    unsigned long long c) {
    unsigned long long d;
    asm("fma.rn.f32x2 %0, %1, %2, %3;" : "=l"(d) : "l"(a), "l"(b), "l"(c));
    return d;
}

// Streaming 8B store (evict-first: output is never re-read; protect L2 halo).
__device__ __forceinline__ void stcs8(float* a, unsigned long long v) {
    asm volatile("st.global.cs.b64 [%0], %1;" :: "l"(a), "l"(v));
}

__global__ void __launch_bounds__(256, 2)
conv_kernel(const float* __restrict__ x, float* __restrict__ out) {
    // PDL: wait for prep_kernel's trigger before touching g_wpair/g_bpair.
    cudaGridDependencySynchronize();

    const int tid = threadIdx.x;          // 0..255
    const int c0 = tid << 1;              // channels c0, c0+1 (contiguous)
    const int p = tid & 3;                // pair type: heads (2p, 2p+1)
    const int b = blockIdx.y;
    const int t0 = blockIdx.x * TT;

    // Weights for this channel pair (packed), resident in registers.
    unsigned long long wk[K_];
    #pragma unroll
    for (int k = 0; k < K_; k++) wk[k] = g_wpair[p][k];

    const unsigned long long bb = g_bpair[p];

    unsigned long long acc[TT];
    #pragma unroll
    for (int j = 0; j < TT; j++) acc[j] = bb;

    const float* xp = x + ((size_t)b * T_) * C_ + c0;

    if (t0 >= PAD_ && t0 + TT + PAD_ <= T_) {
        // Interior fast path: no boundary predicates.
        const float* xq = xp + (size_t)(t0 - PAD_) * C_;
        #pragma unroll
        for (int i = 0; i < TT + 2 * PAD_; i++) {
            const unsigned long long xv =
                *reinterpret_cast<const unsigned long long*>(xq + (size_t)i * C_);
            #pragma unroll
            for (int j = 0; j < TT; j++) {
                if (i - j >= 0 && i - j < K_)   // constant-folds after unroll
                    acc[j] = ffma2(wk[i - j], xv, acc[j]);
            }
        }
        float* op = out + ((size_t)b * T_ + t0) * C_ + c0;
        #pragma unroll
        for (int j = 0; j < TT; j++)
            stcs8(op + (size_t)j * C_, acc[j]);
    } else {
        // Boundary path: zero-padded loads, guarded stores (covers tail block).
        #pragma unroll
        for (int i = 0; i < TT + 2 * PAD_; i++) {
            const int t = t0 - PAD_ + i;
            unsigned long long xv = 0ull;
            if (t >= 0 && t < T_)
                xv = *reinterpret_cast<const unsigned long long*>(xp + (size_t)t * C_);
            #pragma unroll
            for (int j = 0; j < TT; j++) {
                if (i - j >= 0 && i - j < K_)
                    acc[j] = ffma2(wk[i - j], xv, acc[j]);
            }
        }
        float* op = out + ((size_t)b * T_ + t0) * C_ + c0;
        #pragma unroll
        for (int j = 0; j < TT; j++)
            if (t0 + j < T_)
                stcs8(op + (size_t)j * C_, acc[j]);
    }
}

extern "C" void kernel_launch(void* const* d_in, const int* in_sizes, int n_in,
                              void* d_out, int out_size) {
    const float* x    = (const float*)d_in[0];  // (B, T, C)
    const float* w    = (const float*)d_in[1];  // (H, 1, K)
    const float* bias = (const float*)d_in[2];  // (H,)
    float* out = (float*)d_out;                 // (B, T, C)

    prep_kernel<<<1, 128>>>(w, bias);

    // Conv launch with programmatic stream serialization: its grid may begin
    // launching while prep runs; cudaGridDependencySynchronize() in-kernel
    // enforces the data dependency.
    cudaLaunchConfig_t cfg = {};
    cfg.gridDim = dim3((T_ + TT - 1) / TT, B_);
    cfg.blockDim = dim3(256);
    cfg.dynamicSmemBytes = 0;
    cfg.stream = 0;
    cudaLaunchAttribute attrs[1];
    attrs[0].id = cudaLaunchAttributeProgrammaticStreamSerialization;
    attrs[0].val.programmaticStreamSerializationAllowed = 1;
    cfg.attrs = attrs;
    cfg.numAttrs = 1;
    cudaLaunchKernelEx(&cfg, conv_kernel, x, out);
}